// round 5
// baseline (speedup 1.0000x reference)
#include <cuda_runtime.h>
#include <stdint.h>

#define NROI    65536
#define NCASC   3
#define NBATCH  64
#define NROWS   (NBATCH * NCASC)
#define SLICES  8
#define SLICE_ELEMS (NROI / SLICES)        // 8192
#define SCAN_TPB 256
#define SCAN_WARPS (SCAN_TPB / 32)
#define A2_TPB  1024
#define PCAP    128                        // pos candidates per block(slice)
#define NCAP    128                        // neg candidates per block(slice)
#define SELCAP  64
#define TPOSC   0.99f
#define TNEGC   0.99f

#define MODE_LIST    0
#define MODE_ALLELIG 1
#define MODE_SLOW    2

struct Keys { uint32_t k0[3]; uint32_t k1[3]; };
struct RowPar { float mx, tk, top2, kth; int nopos, mode; };

// per-(row,slice) partials — written unconditionally every run (no init needed)
__device__ float  g_pmax [NROWS * SLICES];
__device__ int    g_ppos [NROWS * SLICES];
__device__ int    g_pelig[NROWS * SLICES];
__device__ int    g_pcnt [NROWS * SLICES];
__device__ int    g_ncnt [NROWS * SLICES];
__device__ float  g_posv [NROWS * SLICES * PCAP];
__device__ float  g_negu [NROWS * SLICES * NCAP];
__device__ int    g_negj [NROWS * SLICES * NCAP];
__device__ RowPar g_par  [NROWS];
__device__ int    g_selj [NROWS * SELCAP];
__device__ int    g_selcnt[NROWS];

__device__ const float c_POS_T[3] = {0.6f, 0.7f, 0.8f};
__device__ const float c_IOU_T[3] = {0.2f, 0.3f, 0.4f};
__device__ const float c_NEG_T[3] = {0.3f, 0.3f, 0.3f};

// ---------------------------------------------------------------------------
// JAX threefry2x32 (exact; verified rel_err = 0.0)
// ---------------------------------------------------------------------------
__host__ __device__ __forceinline__ void threefry2x32(
    uint32_t k0, uint32_t k1, uint32_t x0, uint32_t x1,
    uint32_t& o0, uint32_t& o1)
{
    uint32_t ks2 = k0 ^ k1 ^ 0x1BD11BDAu;
    x0 += k0; x1 += k1;
#define TFR(r) { x0 += x1; x1 = (x1 << (r)) | (x1 >> (32 - (r))); x1 ^= x0; }
    TFR(13) TFR(15) TFR(26) TFR(6)  x0 += k1;  x1 += ks2 + 1u;
    TFR(17) TFR(29) TFR(16) TFR(24) x0 += ks2; x1 += k0  + 2u;
    TFR(13) TFR(15) TFR(26) TFR(6)  x0 += k0;  x1 += k1  + 3u;
    TFR(17) TFR(29) TFR(16) TFR(24) x0 += k1;  x1 += ks2 + 4u;
    TFR(13) TFR(15) TFR(26) TFR(6)  x0 += ks2; x1 += k0  + 5u;
#undef TFR
    o0 = x0; o1 = x1;
}

__device__ __forceinline__ float u01(uint32_t k0, uint32_t k1, uint32_t idx)
{
    uint32_t a, c;
    threefry2x32(k0, k1, 0u, idx, a, c);
    uint32_t bits = a ^ c;
    return __uint_as_float((bits >> 9) | 0x3F800000u) - 1.0f;
}

// ---------------------------------------------------------------------------
// Block helpers for the finalize kernel (1024 threads)
// ---------------------------------------------------------------------------
__device__ __forceinline__ int block_reduce_sum_int(int v, int* sc)
{
    int tid = threadIdx.x;
    sc[tid] = v; __syncthreads();
    for (int s = A2_TPB / 2; s > 0; s >>= 1) {
        if (tid < s) sc[tid] += sc[tid + s];
        __syncthreads();
    }
    int r = sc[0];
    __syncthreads();
    return r;
}

__device__ void bitonic_desc(float* a)
{
    int tid = threadIdx.x;
    for (int k = 2; k <= A2_TPB; k <<= 1) {
        for (int j = k >> 1; j > 0; j >>= 1) {
            int ixj = tid ^ j;
            if (ixj > tid) {
                float x = a[tid], y = a[ixj];
                bool desc = ((tid & k) == 0);
                if (desc ? (x < y) : (x > y)) { a[tid] = y; a[ixj] = x; }
            }
            __syncthreads();
        }
    }
}

// ---------------------------------------------------------------------------
// Exact fallbacks (statistically never run; guarantee correctness)
// ---------------------------------------------------------------------------
__device__ float kth_bs_iomask(int k, const float* ov, const float* io,
                               float POS_T, int nopos, float mx, int* sc)
{
    unsigned lo = 0u, hi = 0x7F800000u;
    while (hi > lo) {
        unsigned mid = lo + ((hi - lo + 1u) >> 1);
        float t = __uint_as_float(mid);
        int c = 0;
        for (int j = threadIdx.x; j < NROI; j += A2_TPB) {
            float o = ov[j], v = io[j];
            float im = nopos ? ((v >= mx) ? v : 0.0f)
                             : ((o >= POS_T) ? v : 0.0f);
            c += (im >= t);
        }
        c = block_reduce_sum_int(c, sc);
        if (c >= k) lo = mid; else hi = mid - 1u;
    }
    return __uint_as_float(lo);
}

__device__ float kth_bs_score(int k, const float* ov, float NEG_T,
                              uint32_t k0, uint32_t k1, uint32_t rng_base, int* sc)
{
    unsigned lo = 0u, hi = 0x7F800000u;
    while (hi > lo) {
        unsigned mid = lo + ((hi - lo + 1u) >> 1);
        float t = __uint_as_float(mid);
        int c = 0;
        for (int j = threadIdx.x; j < NROI; j += A2_TPB) {
            float o = ov[j];
            if (o <= NEG_T) {
                float u = u01(k0, k1, rng_base + (uint32_t)j);
                c += (u >= t);
            }
        }
        c = block_reduce_sum_int(c, sc);
        if (c >= k) lo = mid; else hi = mid - 1u;
    }
    return __uint_as_float(lo);
}

// ---------------------------------------------------------------------------
// Kernel A: scan. grid = NROWS*SLICES, 256 threads.
// Register-resident warp compaction of eligible indices (__fns + shfl),
// threefry only on full 32-wide batches. No smem queues, no init pass.
// ---------------------------------------------------------------------------
__global__ __launch_bounds__(SCAN_TPB)
void scan_kernel(const float* __restrict__ g_ov,
                 const float* __restrict__ g_io,
                 Keys keys)
{
    __shared__ int   s_cp, s_cn;
    __shared__ float s_wmax[SCAN_WARPS];
    __shared__ int   s_wpos[SCAN_WARPS];
    __shared__ int   s_welig[SCAN_WARPS];

    const int tid   = threadIdx.x;
    const int wid   = tid >> 5;
    const int lane  = tid & 31;
    const int blk   = blockIdx.x;
    const int r     = blk >> 3;
    const int slice = blk & (SLICES - 1);
    const int h     = r % 3;
    const int b     = r / 3;

    const float POS_T = c_POS_T[h];
    const float NEG_T = c_NEG_T[h];
    const uint32_t k0 = keys.k0[h];
    const uint32_t k1 = keys.k1[h];
    const uint32_t rng_base = (uint32_t)b * (uint32_t)NROI;

    if (tid == 0) { s_cp = 0; s_cn = 0; }
    __syncthreads();

    const float4* ov4 = (const float4*)(g_ov + (size_t)r * NROI) + slice * (SLICE_ELEMS / 4);
    const float4* io4 = (const float4*)(g_io + (size_t)r * NROI) + slice * (SLICE_ELEMS / 4);
    const int j0 = slice * SLICE_ELEMS;

    float lmax = 0.0f;
    int lpos = 0;
    int eligTot = 0;            // warp-uniform
    int cnt = 0;                // warp-uniform buffer fill (0..31)
    uint32_t bufj = 0;          // per-lane buffered eligible index

#pragma unroll
    for (int it = 0; it < SLICE_ELEMS / 4 / SCAN_TPB; it++) {   // 8 iters
        int q = it * SCAN_TPB + tid;
        float4 o4 = ov4[q];
        float4 v4 = io4[q];
        uint32_t jb = (uint32_t)(j0 + q * 4);
#pragma unroll
        for (int l = 0; l < 4; l++) {
            float o = (&o4.x)[l];
            float v = (&v4.x)[l];
            lmax = fmaxf(lmax, v);
            bool pm = (o >= POS_T);
            lpos += pm;
            if (pm && v >= TPOSC) {                 // rare (~0.4% * 0.01)
                int p = atomicAdd(&s_cp, 1);
                if (p < PCAP) g_posv[blk * PCAP + p] = v;
            }
            bool el = (o <= NEG_T);
            uint32_t j = jb + (uint32_t)l;
            unsigned m = __ballot_sync(0xFFFFFFFFu, el);
            int T = __popc(m);
            eligTot += T;
            if (cnt + T >= 32) {
                // complete current batch of 32 and hash it
                int need = 32 - cnt;
                int rk = lane - cnt;
                int rkc = (rk < 0) ? 0 : rk;
                unsigned src = __fns(m, 0u, rkc + 1);
                uint32_t got = __shfl_sync(0xFFFFFFFFu, j, (int)(src & 31u));
                uint32_t myj = (lane >= cnt) ? got : bufj;
                float u = u01(k0, k1, rng_base + myj);
                if (u >= TNEGC) {                   // rare (~1% of batch)
                    int p = atomicAdd(&s_cn, 1);
                    if (p < NCAP) {
                        g_negu[blk * NCAP + p] = u;
                        g_negj[blk * NCAP + p] = (int)myj;
                    }
                }
                int left = T - need;
                unsigned src2 = __fns(m, 0u, lane + need + 1);
                uint32_t got2 = __shfl_sync(0xFFFFFFFFu, j, (int)(src2 & 31u));
                bufj = (lane < left) ? got2 : bufj;
                cnt = left;
            } else {
                int rk = lane - cnt;
                int rkc = (rk < 0) ? 0 : rk;
                unsigned src = __fns(m, 0u, rkc + 1);
                uint32_t got = __shfl_sync(0xFFFFFFFFu, j, (int)(src & 31u));
                bufj = (lane >= cnt && lane < cnt + T) ? got : bufj;
                cnt += T;
            }
        }
    }
    // tail: hash remaining buffered items (predicated)
    if (lane < cnt) {
        float u = u01(k0, k1, rng_base + bufj);
        if (u >= TNEGC) {
            int p = atomicAdd(&s_cn, 1);
            if (p < NCAP) {
                g_negu[blk * NCAP + p] = u;
                g_negj[blk * NCAP + p] = (int)bufj;
            }
        }
    }

    // warp reductions (lmax >= 0 so integer max on bits is valid)
    unsigned wmaxb = __reduce_max_sync(0xFFFFFFFFu, __float_as_uint(lmax));
    unsigned wpos  = __reduce_add_sync(0xFFFFFFFFu, (unsigned)lpos);
    if (lane == 0) {
        s_wmax[wid]  = __uint_as_float(wmaxb);
        s_wpos[wid]  = (int)wpos;
        s_welig[wid] = eligTot;
    }
    __syncthreads();
    if (tid == 0) {
        float mx = 0.0f; int pc = 0, ec = 0;
#pragma unroll
        for (int w = 0; w < SCAN_WARPS; w++) {
            mx = fmaxf(mx, s_wmax[w]);
            pc += s_wpos[w];
            ec += s_welig[w];
        }
        g_pmax[blk] = mx;
        g_ppos[blk] = pc;
        g_pelig[blk] = ec;
        g_pcnt[blk] = s_cp;     // raw (may exceed PCAP -> overflow flag)
        g_ncnt[blk] = s_cn;
    }
}

// ---------------------------------------------------------------------------
// Kernel B: per-row finalize. grid = NROWS, 1024 threads.
// ---------------------------------------------------------------------------
__global__ __launch_bounds__(A2_TPB)
void finalize_kernel(const float* __restrict__ g_ov,
                     const float* __restrict__ g_io,
                     Keys keys)
{
    __shared__ float s_sort[A2_TPB];
    __shared__ int   s_pcnt[SLICES], s_ncnt[SLICES];
    __shared__ float s_mx8[SLICES];
    __shared__ int   s_pos8[SLICES], s_elig8[SLICES];
    __shared__ int   s_sel;
    __shared__ float s_mx;
    __shared__ int   s_poscnt, s_eligcnt, s_cp, s_cn, s_ovfP, s_ovfN;

    const int tid = threadIdx.x;
    const int r = blockIdx.x;
    const int h = r % 3;
    const int b = r / 3;

    const float POS_T = c_POS_T[h];
    const float NEG_T = c_NEG_T[h];
    const float IOU_T = c_IOU_T[h];
    const uint32_t k0 = keys.k0[h];
    const uint32_t k1 = keys.k1[h];
    const uint32_t rng_base = (uint32_t)b * (uint32_t)NROI;

    const float* ov = g_ov + (size_t)r * NROI;
    const float* io = g_io + (size_t)r * NROI;

    if (tid < SLICES) {
        int blk = r * SLICES + tid;
        s_pcnt[tid] = g_pcnt[blk];
        s_ncnt[tid] = g_ncnt[blk];
        s_mx8[tid]  = g_pmax[blk];
        s_pos8[tid] = g_ppos[blk];
        s_elig8[tid]= g_pelig[blk];
    }
    __syncthreads();
    if (tid == 0) {
        float mx = 0.0f; int pc = 0, ec = 0, cp = 0, cn = 0, op = 0, on = 0;
#pragma unroll
        for (int s = 0; s < SLICES; s++) {
            mx = fmaxf(mx, s_mx8[s]); pc += s_pos8[s]; ec += s_elig8[s];
            cp += s_pcnt[s]; cn += s_ncnt[s];
            op |= (s_pcnt[s] > PCAP); on |= (s_ncnt[s] > NCAP);
        }
        s_mx = mx; s_poscnt = pc; s_eligcnt = ec;
        s_cp = cp; s_cn = cn; s_ovfP = op; s_ovfN = on;
    }
    __syncthreads();

    const float mx = s_mx;
    const int poscnt = s_poscnt, eligcnt = s_eligcnt;
    const int cp = s_cp, cn = s_cn, ovfP = s_ovfP, ovfN = s_ovfN;

    // -------- positive threshold: 16th (+2nd) largest of iou_masked --------
    int nopos = (poscnt == 0);
    float t16, top2 = 0.0f;
    if (!nopos && cp >= 16 && !ovfP) {
        int sl = tid >> 7, i = tid & (PCAP - 1);
        s_sort[tid] = (i < s_pcnt[sl]) ? g_posv[(r * SLICES + sl) * PCAP + i] : -1.0f;
        __syncthreads();
        bitonic_desc(s_sort);
        t16 = s_sort[15];
        top2 = s_sort[1];
        __syncthreads();
    } else {
        t16 = kth_bs_iomask(16, ov, io, POS_T, nopos, mx, (int*)s_sort);
        if (h == 0) top2 = kth_bs_iomask(2, ov, io, POS_T, nopos, mx, (int*)s_sort);
    }
    float tk = (t16 >= IOU_T) ? t16 : IOU_T;

    // -------- negative threshold: 48th largest random score among eligible --
    float kth = -1.0f;
    int mode;
    int selcnt = 0;
    if (eligcnt < 48) {
        mode = MODE_ALLELIG;                 // kth = -inf: all eligible neg
    } else if (cn >= 48 && !ovfN) {
        int sl = tid >> 7, i = tid & (NCAP - 1);
        bool valid = (i < s_ncnt[sl]);
        float u = valid ? g_negu[(r * SLICES + sl) * NCAP + i] : -1.0f;
        s_sort[tid] = u;
        __syncthreads();
        bitonic_desc(s_sort);
        kth = s_sort[47];
        __syncthreads();
        if (tid == 0) s_sel = 0;
        __syncthreads();
        if (valid && u >= kth) {
            int p = atomicAdd(&s_sel, 1);
            if (p < SELCAP)
                g_selj[r * SELCAP + p] = g_negj[(r * SLICES + sl) * NCAP + i];
        }
        __syncthreads();
        selcnt = s_sel;
        if (selcnt > SELCAP) { mode = MODE_SLOW; selcnt = 0; }  // kth exact
        else mode = MODE_LIST;
    } else {
        mode = MODE_SLOW;
        kth = kth_bs_score(48, ov, NEG_T, k0, k1, rng_base, (int*)s_sort);
    }

    if (tid == 0) {
        g_selcnt[r] = selcnt;
        RowPar p;
        p.mx = mx; p.tk = tk; p.top2 = top2; p.kth = kth;
        p.nopos = nopos; p.mode = mode;
        g_par[r] = p;
    }
}

// ---------------------------------------------------------------------------
// Kernel C: elementwise labels. 2 float4 per thread for MLP.
// grid = NROWS * 32 blocks, 256 threads; each block owns 512 float4 of a row.
// ---------------------------------------------------------------------------
__global__ __launch_bounds__(256)
void label_kernel(const float* __restrict__ g_ov,
                  const float* __restrict__ g_io,
                  const float* __restrict__ g_nm,
                  float* __restrict__ g_out,
                  Keys keys)
{
    const int tid = threadIdx.x;
    const int r = blockIdx.x >> 5;
    const int chunk = blockIdx.x & 31;
    const int h = r % 3;

    RowPar p = g_par[r];
    const float POS_T = c_POS_T[h];
    const float NEG_T = c_NEG_T[h];
    const uint32_t rng_base = (uint32_t)(r / 3) * (uint32_t)NROI;

    const float4* ov4 = (const float4*)(g_ov + (size_t)r * NROI);
    const float4* io4 = (const float4*)(g_io + (size_t)r * NROI);
    const float*  nm  = g_nm + (size_t)r * NROI;
    float4*       out4 = (float4*)(g_out + (size_t)r * NROI);

    int qa = chunk * 512 + tid;
    int qb = qa + 256;
    float4 oA = ov4[qa], vA = io4[qa];
    float4 oB = ov4[qb], vB = io4[qb];

#pragma unroll
    for (int half = 0; half < 2; half++) {
        float4 o4 = half ? oB : oA;
        float4 v4 = half ? vB : vA;
        int q = half ? qb : qa;
        int jb = q * 4;
        float4 res;
#pragma unroll
        for (int l = 0; l < 4; l++) {
            float o = (&o4.x)[l];
            float v = (&v4.x)[l];
            float im = p.nopos ? ((v >= p.mx) ? v : 0.0f)
                               : ((o >= POS_T) ? v : 0.0f);
            bool posb = (im >= p.tk);
            if (h == 0) posb = posb || (im > p.top2);
            float posf = 0.0f;
            if (posb) posf = nm[jb + l];           // rare scalar load

            float negf = 0.0f;
            if (p.mode == MODE_ALLELIG) {
                negf = (o <= NEG_T) ? 1.0f : 0.0f;
            } else if (p.mode == MODE_SLOW) {
                if (o <= NEG_T) {
                    float u = u01(keys.k0[h], keys.k1[h],
                                  rng_base + (uint32_t)(jb + l));
                    if (u >= p.kth) negf = 1.0f;
                }
            }
            (&res.x)[l] = (-1.0f + negf) + 2.0f * posf;
        }
        out4[q] = res;
    }
}

// ---------------------------------------------------------------------------
// Kernel D: scatter-overwrite selected negatives (LIST mode only)
// ---------------------------------------------------------------------------
__global__ void scatter_kernel(const float* __restrict__ g_ov,
                               const float* __restrict__ g_io,
                               const float* __restrict__ g_nm,
                               float* __restrict__ g_out)
{
    int r = blockIdx.x;
    int h = r % 3;
    RowPar p = g_par[r];
    int cnt = g_selcnt[r];
    const float POS_T = c_POS_T[h];
    size_t rowoff = (size_t)r * NROI;

    for (int i = threadIdx.x; i < cnt; i += blockDim.x) {
        int j = g_selj[r * SELCAP + i];
        float o = g_ov[rowoff + j];
        float v = g_io[rowoff + j];
        float im = p.nopos ? ((v >= p.mx) ? v : 0.0f)
                           : ((o >= POS_T) ? v : 0.0f);
        bool posb = (im >= p.tk);
        if (h == 0) posb = posb || (im > p.top2);
        float posf = 0.0f;
        if (posb) posf = g_nm[rowoff + j];
        g_out[rowoff + j] = 2.0f * posf;           // -1 + 1 + 2*pos
    }
}

// ---------------------------------------------------------------------------
// Launch
// ---------------------------------------------------------------------------
extern "C" void kernel_launch(void* const* d_in, const int* in_sizes, int n_in,
                              void* d_out, int out_size)
{
    const float* ov = (const float*)d_in[0];
    const float* io = (const float*)d_in[1];
    const float* nm = (const float*)d_in[2];
    float* out = (float*)d_out;

    Keys keys;
    for (int h = 0; h < NCASC; h++) {
        uint32_t a, c;
        threefry2x32(0u, 42u, 0u, (uint32_t)h, a, c);
        keys.k0[h] = a;
        keys.k1[h] = c;
    }

    scan_kernel<<<NROWS * SLICES, SCAN_TPB>>>(ov, io, keys);
    finalize_kernel<<<NROWS, A2_TPB>>>(ov, io, keys);
    label_kernel<<<NROWS * 32, 256>>>(ov, io, nm, out, keys);
    scatter_kernel<<<NROWS, 64>>>(ov, io, nm, out);
}

// round 6
// speedup vs baseline: 1.5729x; 1.5729x over previous
#include <cuda_runtime.h>
#include <stdint.h>

#define NROI    65536
#define NCASC   3
#define NBATCH  64
#define NROWS   (NBATCH * NCASC)
#define SLICES  8
#define SLICE_ELEMS (NROI / SLICES)        // 8192
#define SCAN_TPB 128
#define SCAN_WARPS (SCAN_TPB / 32)         // 4
#define WCHUNK  (SLICE_ELEMS / SCAN_WARPS) // 2048 elements per warp
#define A2_TPB  1024
#define PCAP    128                        // pos candidates per (row,slice)
#define NCAP    128                        // neg candidates per (row,slice)
#define BITWORDS (NROI / 32)               // 2048 words per row
#define TPOSC   0.99f
#define TNEGC   0.99f

#define MODE_LIST    0
#define MODE_ALLELIG 1
#define MODE_SLOW    2

struct Keys { uint32_t k0[3]; uint32_t k1[3]; };
struct RowPar { float mx, tk, top2, kth; int nopos, mode; };

// per-(row,slice) partials — written unconditionally every run (no init pass)
__device__ float  g_pmax [NROWS * SLICES];
__device__ int    g_ppos [NROWS * SLICES];
__device__ int    g_pelig[NROWS * SLICES];
__device__ int    g_pcnt [NROWS * SLICES];
__device__ int    g_ncnt [NROWS * SLICES];
__device__ float  g_posv [NROWS * SLICES * PCAP];
__device__ float  g_negu [NROWS * SLICES * NCAP];
__device__ int    g_negj [NROWS * SLICES * NCAP];
__device__ RowPar g_par  [NROWS];
__device__ unsigned g_negbit[NROWS * BITWORDS];   // 1.5 MB selected-neg bitmap

__device__ const float c_POS_T[3] = {0.6f, 0.7f, 0.8f};
__device__ const float c_IOU_T[3] = {0.2f, 0.3f, 0.4f};
__device__ const float c_NEG_T[3] = {0.3f, 0.3f, 0.3f};

// ---------------------------------------------------------------------------
// JAX threefry2x32 (exact; verified rel_err = 0.0)
// ---------------------------------------------------------------------------
__host__ __device__ __forceinline__ void threefry2x32(
    uint32_t k0, uint32_t k1, uint32_t x0, uint32_t x1,
    uint32_t& o0, uint32_t& o1)
{
    uint32_t ks2 = k0 ^ k1 ^ 0x1BD11BDAu;
    x0 += k0; x1 += k1;
#define TFR(r) { x0 += x1; x1 = (x1 << (r)) | (x1 >> (32 - (r))); x1 ^= x0; }
    TFR(13) TFR(15) TFR(26) TFR(6)  x0 += k1;  x1 += ks2 + 1u;
    TFR(17) TFR(29) TFR(16) TFR(24) x0 += ks2; x1 += k0  + 2u;
    TFR(13) TFR(15) TFR(26) TFR(6)  x0 += k0;  x1 += k1  + 3u;
    TFR(17) TFR(29) TFR(16) TFR(24) x0 += k1;  x1 += ks2 + 4u;
    TFR(13) TFR(15) TFR(26) TFR(6)  x0 += ks2; x1 += k0  + 5u;
#undef TFR
    o0 = x0; o1 = x1;
}

__device__ __forceinline__ float u01(uint32_t k0, uint32_t k1, uint32_t idx)
{
    uint32_t a, c;
    threefry2x32(k0, k1, 0u, idx, a, c);
    uint32_t bits = a ^ c;
    return __uint_as_float((bits >> 9) | 0x3F800000u) - 1.0f;
}

// ---------------------------------------------------------------------------
// Block helpers (finalize kernel, 1024 threads)
// ---------------------------------------------------------------------------
__device__ __forceinline__ int block_reduce_sum_int(int v, int* sc)
{
    int tid = threadIdx.x;
    sc[tid] = v; __syncthreads();
    for (int s = A2_TPB / 2; s > 0; s >>= 1) {
        if (tid < s) sc[tid] += sc[tid + s];
        __syncthreads();
    }
    int r = sc[0];
    __syncthreads();
    return r;
}

__device__ void bitonic_desc(float* a)
{
    int tid = threadIdx.x;
    for (int k = 2; k <= A2_TPB; k <<= 1) {
        for (int j = k >> 1; j > 0; j >>= 1) {
            int ixj = tid ^ j;
            if (ixj > tid) {
                float x = a[tid], y = a[ixj];
                bool desc = ((tid & k) == 0);
                if (desc ? (x < y) : (x > y)) { a[tid] = y; a[ixj] = x; }
            }
            __syncthreads();
        }
    }
}

// ---------------------------------------------------------------------------
// Exact fallbacks (statistically never run; guarantee correctness)
// ---------------------------------------------------------------------------
__device__ float kth_bs_iomask(int k, const float* ov, const float* io,
                               float POS_T, int nopos, float mx, int* sc)
{
    unsigned lo = 0u, hi = 0x7F800000u;
    while (hi > lo) {
        unsigned mid = lo + ((hi - lo + 1u) >> 1);
        float t = __uint_as_float(mid);
        int c = 0;
        for (int j = threadIdx.x; j < NROI; j += A2_TPB) {
            float o = ov[j], v = io[j];
            float im = nopos ? ((v >= mx) ? v : 0.0f)
                             : ((o >= POS_T) ? v : 0.0f);
            c += (im >= t);
        }
        c = block_reduce_sum_int(c, sc);
        if (c >= k) lo = mid; else hi = mid - 1u;
    }
    return __uint_as_float(lo);
}

__device__ float kth_bs_score(int k, const float* ov, float NEG_T,
                              uint32_t k0, uint32_t k1, uint32_t rng_base, int* sc)
{
    unsigned lo = 0u, hi = 0x7F800000u;
    while (hi > lo) {
        unsigned mid = lo + ((hi - lo + 1u) >> 1);
        float t = __uint_as_float(mid);
        int c = 0;
        for (int j = threadIdx.x; j < NROI; j += A2_TPB) {
            float o = ov[j];
            if (o <= NEG_T) {
                float u = u01(k0, k1, rng_base + (uint32_t)j);
                c += (u >= t);
            }
        }
        c = block_reduce_sum_int(c, sc);
        if (c >= k) lo = mid; else hi = mid - 1u;
    }
    return __uint_as_float(lo);
}

// ---------------------------------------------------------------------------
// Kernel A: scan. grid = NROWS*SLICES, 128 threads (4 warps x 2048 elements).
// Phase A: write ALL eligible local indices to a worst-case-sized per-warp
//          smem queue (no atomics, no overflow checks, no divergence).
// Phase B: drain queue, hashing dense 32-wide batches.
// ---------------------------------------------------------------------------
__global__ __launch_bounds__(SCAN_TPB)
void scan_kernel(const float* __restrict__ g_ov,
                 const float* __restrict__ g_io,
                 Keys keys)
{
    __shared__ uint16_t s_q[SCAN_WARPS][WCHUNK];   // 16 KB
    __shared__ int   s_cp, s_cn;
    __shared__ float s_wmax[SCAN_WARPS];
    __shared__ int   s_wpos[SCAN_WARPS];
    __shared__ int   s_welig[SCAN_WARPS];

    const int tid   = threadIdx.x;
    const int wid   = tid >> 5;
    const int lane  = tid & 31;
    const int blk   = blockIdx.x;
    const int r     = blk >> 3;
    const int slice = blk & (SLICES - 1);
    const int h     = r % 3;
    const int b     = r / 3;

    const float POS_T = c_POS_T[h];
    const float NEG_T = c_NEG_T[h];
    const uint32_t k0 = keys.k0[h];
    const uint32_t k1 = keys.k1[h];
    const uint32_t rng_base = (uint32_t)b * (uint32_t)NROI;

    if (tid == 0) { s_cp = 0; s_cn = 0; }
    __syncthreads();

    // warp-chunk base (element index within row)
    const int chunk0 = slice * SLICE_ELEMS + wid * WCHUNK;
    const float4* ov4 = (const float4*)(g_ov + (size_t)r * NROI) + (chunk0 >> 2);
    const float4* io4 = (const float4*)(g_io + (size_t)r * NROI) + (chunk0 >> 2);

    const unsigned lmask = (1u << lane) - 1u;
    float lmax = 0.0f;
    int lpos = 0;
    int cnt = 0;                 // warp-uniform queue fill

    // ---------- Phase A: scan + compact to smem queue ----------
#pragma unroll 4
    for (int it = 0; it < WCHUNK / 4 / 32; it++) {   // 16 iters
        int q = it * 32 + lane;
        float4 o4 = ov4[q];
        float4 v4 = io4[q];
        int local = q * 4;       // 0..2047 within warp chunk
#pragma unroll
        for (int l = 0; l < 4; l++) {
            float o = (&o4.x)[l];
            float v = (&v4.x)[l];
            lmax = fmaxf(lmax, v);
            bool pm = (o >= POS_T);
            lpos += pm;
            if (pm && v >= TPOSC) {                 // ~0.4% of elements
                int p = atomicAdd(&s_cp, 1);
                if (p < PCAP) g_posv[blk * PCAP + p] = v;
            }
            bool el = (o <= NEG_T);
            unsigned m = __ballot_sync(0xFFFFFFFFu, el);
            if (el) s_q[wid][cnt + __popc(m & lmask)] = (uint16_t)(local + l);
            cnt += __popc(m);
        }
    }
    __syncwarp();

    // ---------- Phase B: dense hashing of compacted queue ----------
    const uint32_t jwbase = rng_base + (uint32_t)chunk0;
    for (int t = lane; t < cnt; t += 32) {
        uint32_t idx = (uint32_t)s_q[wid][t];
        float u = u01(k0, k1, jwbase + idx);
        if (u >= TNEGC) {                           // ~1% of eligible
            int p = atomicAdd(&s_cn, 1);
            if (p < NCAP) {
                g_negu[blk * NCAP + p] = u;
                g_negj[blk * NCAP + p] = (int)(chunk0 + idx);   // row-relative
            }
        }
    }

    // ---------- reductions ----------
    unsigned wmaxb = __reduce_max_sync(0xFFFFFFFFu, __float_as_uint(lmax));
    unsigned wpos  = __reduce_add_sync(0xFFFFFFFFu, (unsigned)lpos);
    if (lane == 0) {
        s_wmax[wid]  = __uint_as_float(wmaxb);
        s_wpos[wid]  = (int)wpos;
        s_welig[wid] = cnt;
    }
    __syncthreads();
    if (tid == 0) {
        float mx = 0.0f; int pc = 0, ec = 0;
#pragma unroll
        for (int w = 0; w < SCAN_WARPS; w++) {
            mx = fmaxf(mx, s_wmax[w]);
            pc += s_wpos[w];
            ec += s_welig[w];
        }
        g_pmax[blk] = mx;
        g_ppos[blk] = pc;
        g_pelig[blk] = ec;
        g_pcnt[blk] = s_cp;     // raw (may exceed PCAP -> overflow flag)
        g_ncnt[blk] = s_cn;
    }
}

// ---------------------------------------------------------------------------
// Kernel B: per-row finalize. grid = NROWS, 1024 threads.
// Computes thresholds and writes the selected-negatives bitmap.
// ---------------------------------------------------------------------------
__global__ __launch_bounds__(A2_TPB)
void finalize_kernel(const float* __restrict__ g_ov,
                     const float* __restrict__ g_io,
                     Keys keys)
{
    __shared__ float s_sort[A2_TPB];
    __shared__ int   s_pcnt[SLICES], s_ncnt[SLICES];
    __shared__ float s_mx8[SLICES];
    __shared__ int   s_pos8[SLICES], s_elig8[SLICES];
    __shared__ float s_mx;
    __shared__ int   s_poscnt, s_eligcnt, s_cp, s_cn, s_ovfP, s_ovfN;

    const int tid = threadIdx.x;
    const int r = blockIdx.x;
    const int h = r % 3;
    const int b = r / 3;

    const float POS_T = c_POS_T[h];
    const float NEG_T = c_NEG_T[h];
    const float IOU_T = c_IOU_T[h];
    const uint32_t k0 = keys.k0[h];
    const uint32_t k1 = keys.k1[h];
    const uint32_t rng_base = (uint32_t)b * (uint32_t)NROI;

    const float* ov = g_ov + (size_t)r * NROI;
    const float* io = g_io + (size_t)r * NROI;

    if (tid < SLICES) {
        int blk = r * SLICES + tid;
        s_pcnt[tid] = g_pcnt[blk];
        s_ncnt[tid] = g_ncnt[blk];
        s_mx8[tid]  = g_pmax[blk];
        s_pos8[tid] = g_ppos[blk];
        s_elig8[tid]= g_pelig[blk];
    }
    __syncthreads();
    if (tid == 0) {
        float mx = 0.0f; int pc = 0, ec = 0, cp = 0, cn = 0, op = 0, on = 0;
#pragma unroll
        for (int s = 0; s < SLICES; s++) {
            mx = fmaxf(mx, s_mx8[s]); pc += s_pos8[s]; ec += s_elig8[s];
            cp += s_pcnt[s]; cn += s_ncnt[s];
            op |= (s_pcnt[s] > PCAP); on |= (s_ncnt[s] > NCAP);
        }
        s_mx = mx; s_poscnt = pc; s_eligcnt = ec;
        s_cp = cp; s_cn = cn; s_ovfP = op; s_ovfN = on;
    }
    __syncthreads();

    const float mx = s_mx;
    const int poscnt = s_poscnt, eligcnt = s_eligcnt;
    const int cp = s_cp, cn = s_cn, ovfP = s_ovfP, ovfN = s_ovfN;

    // -------- positive threshold: 16th (+2nd) largest of iou_masked --------
    int nopos = (poscnt == 0);
    float t16, top2 = 0.0f;
    if (!nopos && cp >= 16 && !ovfP) {
        int sl = tid >> 7, i = tid & (PCAP - 1);
        s_sort[tid] = (i < s_pcnt[sl]) ? g_posv[(r * SLICES + sl) * PCAP + i] : -1.0f;
        __syncthreads();
        bitonic_desc(s_sort);
        t16 = s_sort[15];
        top2 = s_sort[1];
        __syncthreads();
    } else {
        t16 = kth_bs_iomask(16, ov, io, POS_T, nopos, mx, (int*)s_sort);
        if (h == 0) top2 = kth_bs_iomask(2, ov, io, POS_T, nopos, mx, (int*)s_sort);
    }
    float tk = (t16 >= IOU_T) ? t16 : IOU_T;

    // -------- negative threshold: 48th largest random score among eligible --
    float kth = -1.0f;
    int mode;
    if (eligcnt < 48) {
        mode = MODE_ALLELIG;                 // kth = -inf: all eligible neg
    } else if (cn >= 48 && !ovfN) {
        mode = MODE_LIST;
        int sl = tid >> 7, i = tid & (NCAP - 1);
        bool valid = (i < s_ncnt[sl]);
        float u_reg = valid ? g_negu[(r * SLICES + sl) * NCAP + i] : -1.0f;
        int   j_reg = valid ? g_negj[(r * SLICES + sl) * NCAP + i] : 0;
        s_sort[tid] = u_reg;
        __syncthreads();
        bitonic_desc(s_sort);
        kth = s_sort[47];
        __syncthreads();
        // write bitmap: zero then set selected bits
        for (int i2 = tid; i2 < BITWORDS; i2 += A2_TPB)
            g_negbit[r * BITWORDS + i2] = 0u;
        __syncthreads();
        if (valid && u_reg >= kth)
            atomicOr(&g_negbit[r * BITWORDS + (j_reg >> 5)],
                     1u << (j_reg & 31));
    } else {
        mode = MODE_SLOW;
        kth = kth_bs_score(48, ov, NEG_T, k0, k1, rng_base, (int*)s_sort);
    }

    if (tid == 0) {
        RowPar p;
        p.mx = mx; p.tk = tk; p.top2 = top2; p.kth = kth;
        p.nopos = nopos; p.mode = mode;
        g_par[r] = p;
    }
}

// ---------------------------------------------------------------------------
// Kernel C: elementwise labels. Negatives come from the bitmap (LIST mode).
// 2 float4 per thread for MLP. grid = NROWS*32, 256 threads.
// ---------------------------------------------------------------------------
__global__ __launch_bounds__(256)
void label_kernel(const float* __restrict__ g_ov,
                  const float* __restrict__ g_io,
                  const float* __restrict__ g_nm,
                  float* __restrict__ g_out,
                  Keys keys)
{
    const int tid = threadIdx.x;
    const int r = blockIdx.x >> 5;
    const int chunk = blockIdx.x & 31;
    const int h = r % 3;

    RowPar p = g_par[r];
    const float POS_T = c_POS_T[h];
    const float NEG_T = c_NEG_T[h];
    const uint32_t rng_base = (uint32_t)(r / 3) * (uint32_t)NROI;

    const float4* ov4 = (const float4*)(g_ov + (size_t)r * NROI);
    const float4* io4 = (const float4*)(g_io + (size_t)r * NROI);
    const float*  nm  = g_nm + (size_t)r * NROI;
    float4*       out4 = (float4*)(g_out + (size_t)r * NROI);

    int qa = chunk * 512 + tid;
    int qb = qa + 256;
    float4 oA = ov4[qa], vA = io4[qa];
    float4 oB = ov4[qb], vB = io4[qb];

#pragma unroll
    for (int half = 0; half < 2; half++) {
        float4 o4 = half ? oB : oA;
        float4 v4 = half ? vB : vA;
        int q = half ? qb : qa;
        int jb = q * 4;                       // row-relative element index
        unsigned w = 0u;
        if (p.mode == MODE_LIST)
            w = g_negbit[r * BITWORDS + (jb >> 5)];
        float4 res;
#pragma unroll
        for (int l = 0; l < 4; l++) {
            float o = (&o4.x)[l];
            float v = (&v4.x)[l];
            float im = p.nopos ? ((v >= p.mx) ? v : 0.0f)
                               : ((o >= POS_T) ? v : 0.0f);
            bool posb = (im >= p.tk);
            if (h == 0) posb = posb || (im > p.top2);
            float posf = 0.0f;
            if (posb) posf = nm[jb + l];      // rare scalar load

            float negf;
            if (p.mode == MODE_LIST) {
                negf = (float)((w >> ((jb & 31) + l)) & 1u);
            } else if (p.mode == MODE_ALLELIG) {
                negf = (o <= NEG_T) ? 1.0f : 0.0f;
            } else {
                negf = 0.0f;
                if (o <= NEG_T) {
                    float u = u01(keys.k0[h], keys.k1[h],
                                  rng_base + (uint32_t)(jb + l));
                    if (u >= p.kth) negf = 1.0f;
                }
            }
            (&res.x)[l] = (-1.0f + negf) + 2.0f * posf;
        }
        out4[q] = res;
    }
}

// ---------------------------------------------------------------------------
// Launch
// ---------------------------------------------------------------------------
extern "C" void kernel_launch(void* const* d_in, const int* in_sizes, int n_in,
                              void* d_out, int out_size)
{
    const float* ov = (const float*)d_in[0];
    const float* io = (const float*)d_in[1];
    const float* nm = (const float*)d_in[2];
    float* out = (float*)d_out;

    Keys keys;
    for (int h = 0; h < NCASC; h++) {
        uint32_t a, c;
        threefry2x32(0u, 42u, 0u, (uint32_t)h, a, c);
        keys.k0[h] = a;
        keys.k1[h] = c;
    }

    scan_kernel<<<NROWS * SLICES, SCAN_TPB>>>(ov, io, keys);
    finalize_kernel<<<NROWS, A2_TPB>>>(ov, io, keys);
    label_kernel<<<NROWS * 32, 256>>>(ov, io, nm, out, keys);
}